// round 1
// baseline (speedup 1.0000x reference)
#include <cuda_runtime.h>
#include <math.h>
#include <float.h>

#define B 256
#define N 2048
#define M 64
#define C 512
#define OUTD 198   // 3*M + 6

// Param scratch layout per batch (stride 208):
//  [0..63]  k (raw)
//  [64..127] e = sigmoid(o[70..133])
//  [128..191] a = o[134..197]
//  [192] beta  [193] g  [194] gamma  [195..197] s0,s1,s2  [198] ||k+eps||
#define P_STRIDE 208
__device__ float g_params[B * P_STRIDE];
__device__ float g_scores[B * N];

__device__ __forceinline__ float softplus_f(float x) {
    return (x > 20.f) ? x : log1pf(expf(x));
}
__device__ __forceinline__ float sigmoid_f(float x) {
    return 1.f / (1.f + expf(-x));
}

// ---------------------------------------------------------------------------
// Kernel 1: controller projection o = h @ W^T + b, activations, k-norm.
// One block per batch row. 256 threads (8 warps); warp j computes outputs
// j, j+8, ... each as a coalesced dot over C=512.
// ---------------------------------------------------------------------------
__global__ void k_proj(const float* __restrict__ h,
                       const float* __restrict__ Wm,
                       const float* __restrict__ bias) {
    int b = blockIdx.x;
    __shared__ float sh[C];
    __shared__ float so[OUTD];

    for (int i = threadIdx.x; i < C; i += 256) sh[i] = h[b * C + i];
    __syncthreads();

    int warp = threadIdx.x >> 5, lane = threadIdx.x & 31;
    for (int j = warp; j < OUTD; j += 8) {
        const float* wr = Wm + (size_t)j * C;
        float acc = 0.f;
        #pragma unroll 4
        for (int c = lane; c < C; c += 32) acc += wr[c] * sh[c];
        #pragma unroll
        for (int o = 16; o; o >>= 1) acc += __shfl_xor_sync(0xffffffffu, acc, o);
        if (lane == 0) so[j] = acc + bias[j];
    }
    __syncthreads();

    float* p = g_params + b * P_STRIDE;
    int t = threadIdx.x;
    if (t < 64) {
        p[t] = so[t];                                  // k
    } else if (t < 128) {
        p[t] = sigmoid_f(so[70 + (t - 64)]);           // e
    } else if (t < 192) {
        p[t] = so[134 + (t - 128)];                    // a
    } else if (t == 192) {
        p[192] = softplus_f(so[64]);                   // beta
        p[193] = sigmoid_f(so[65]);                    // g
        p[194] = 1.f + softplus_f(so[69]);             // gamma
        float s0 = so[66], s1 = so[67], s2 = so[68];
        float mx = fmaxf(s0, fmaxf(s1, s2));
        float e0 = expf(s0 - mx), e1 = expf(s1 - mx), e2 = expf(s2 - mx);
        float inv = 1.f / (e0 + e1 + e2);
        p[195] = e0 * inv; p[196] = e1 * inv; p[197] = e2 * inv;
    }
    // ||k + 1e-16|| by warp 0 (reads so[], which is stable after the sync)
    if (warp == 0) {
        float v0 = so[lane] + 1e-16f;
        float v1 = so[lane + 32] + 1e-16f;
        float acc = v0 * v0 + v1 * v1;
        #pragma unroll
        for (int o = 16; o; o >>= 1) acc += __shfl_xor_sync(0xffffffffu, acc, o);
        if (lane == 0) p[198] = sqrtf(acc);
    }
}

// ---------------------------------------------------------------------------
// Kernel 2: content-addressing scores. Streams memory (134 MB) once.
// Each warp handles 2 rows; 16 lanes per row, float4 loads (256 B / row).
// Block = 256 threads = 16 rows; N % 16 == 0 so one batch per block.
// ---------------------------------------------------------------------------
__global__ void k_score(const float* __restrict__ memory) {
    int warp = threadIdx.x >> 5, lane = threadIdx.x & 31;
    size_t row = (size_t)blockIdx.x * 16 + warp * 2 + (lane >> 4);
    int b = (int)(row >> 11);   // N = 2048

    __shared__ float sk[64];
    __shared__ float sbk[2];    // beta, knorm
    if (threadIdx.x < 64) sk[threadIdx.x] = g_params[b * P_STRIDE + threadIdx.x] + 1e-16f;
    if (threadIdx.x == 64) sbk[0] = g_params[b * P_STRIDE + 192];
    if (threadIdx.x == 65) sbk[1] = g_params[b * P_STRIDE + 198];
    __syncthreads();

    int q = lane & 15;
    float4 m = ((const float4*)(memory + row * 64))[q];
    float4 kv = ((const float4*)sk)[q];
    float x0 = m.x + 1e-16f, x1 = m.y + 1e-16f, x2 = m.z + 1e-16f, x3 = m.w + 1e-16f;
    float dot = x0 * kv.x + x1 * kv.y + x2 * kv.z + x3 * kv.w;
    float nrm = x0 * x0 + x1 * x1 + x2 * x2 + x3 * x3;
    #pragma unroll
    for (int o = 8; o; o >>= 1) {
        dot += __shfl_xor_sync(0xffffffffu, dot, o);
        nrm += __shfl_xor_sync(0xffffffffu, nrm, o);
    }
    if (q == 0) {
        float denom = fmaxf(sqrtf(nrm) * sbk[1], 1e-8f);
        g_scores[row] = sbk[0] * dot / denom;
    }
}

// ---------------------------------------------------------------------------
// Kernel 3: per-batch addressing: softmax(scores), gate with w_prev,
// circular 3-tap shift, sharpen (pow gamma), renormalize -> w (into d_out).
// One block per batch, 512 threads, 4 elements/thread.
// ---------------------------------------------------------------------------
__device__ __forceinline__ float blockReduce(float v, float* red, bool is_max) {
    int lane = threadIdx.x & 31, wid = threadIdx.x >> 5;
    #pragma unroll
    for (int o = 16; o; o >>= 1) {
        float t = __shfl_xor_sync(0xffffffffu, v, o);
        v = is_max ? fmaxf(v, t) : (v + t);
    }
    if (lane == 0) red[wid] = v;
    __syncthreads();
    float r = (threadIdx.x < 16) ? red[threadIdx.x] : (is_max ? -FLT_MAX : 0.f);
    if (wid == 0) {
        #pragma unroll
        for (int o = 8; o; o >>= 1) {
            float t = __shfl_xor_sync(0xffffffffu, r, o);
            r = is_max ? fmaxf(r, t) : (r + t);
        }
        if (lane == 0) red[0] = r;
    }
    __syncthreads();
    float out = red[0];
    __syncthreads();
    return out;
}

__global__ void k_addr(const float* __restrict__ w_prev, float* __restrict__ w_out) {
    int b = blockIdx.x;
    __shared__ float sw[N];
    __shared__ float red[32];

    const float* sc = g_scores + (size_t)b * N;
    const float* p = g_params + b * P_STRIDE;
    int t = threadIdx.x;

    float v[4];
    float mx = -FLT_MAX;
    #pragma unroll
    for (int i = 0; i < 4; i++) { v[i] = sc[t + i * 512]; mx = fmaxf(mx, v[i]); }
    mx = blockReduce(mx, red, true);

    float sum = 0.f;
    #pragma unroll
    for (int i = 0; i < 4; i++) { v[i] = expf(v[i] - mx); sum += v[i]; }
    sum = blockReduce(sum, red, false);
    float inv = 1.f / sum;

    float g = p[193];
    #pragma unroll
    for (int i = 0; i < 4; i++) {
        int idx = t + i * 512;
        sw[idx] = g * (v[i] * inv) + (1.f - g) * w_prev[(size_t)b * N + idx];
    }
    __syncthreads();

    float s0 = p[195], s1 = p[196], s2 = p[197], gamma = p[194];
    float u[4];
    float psum = 0.f;
    #pragma unroll
    for (int i = 0; i < 4; i++) {
        int idx = t + i * 512;
        float wt = sw[(idx + N - 1) & (N - 1)] * s0 + sw[idx] * s1 + sw[(idx + 1) & (N - 1)] * s2;
        float ws = powf(wt, gamma);
        u[i] = ws; psum += ws;
    }
    psum = blockReduce(psum, red, false);
    float invp = 1.f / (psum + 1e-16f);
    #pragma unroll
    for (int i = 0; i < 4; i++)
        w_out[(size_t)b * N + t + i * 512] = u[i] * invp;
}

// ---------------------------------------------------------------------------
// Kernel 4: erase/add write: mem_new = memory*(1 - w (x) e) + w (x) a.
// float4 per thread; w broadcast per row; e/a hit L1.
// ---------------------------------------------------------------------------
__global__ void k_write(const float* __restrict__ memory,
                        const float* __restrict__ w,
                        float* __restrict__ mem_out) {
    size_t i4 = (size_t)blockIdx.x * 256 + threadIdx.x;   // float4 index
    int m4 = (int)(i4 & 15);
    size_t row = i4 >> 4;
    int b = (int)(row >> 11);

    float wv = __ldg(w + row);
    const float* p = g_params + b * P_STRIDE;
    float4 e4 = ((const float4*)(p + 64))[m4];
    float4 a4 = ((const float4*)(p + 128))[m4];
    float4 m = ((const float4*)memory)[i4];
    float4 o;
    o.x = m.x * (1.f - wv * e4.x) + wv * a4.x;
    o.y = m.y * (1.f - wv * e4.y) + wv * a4.y;
    o.z = m.z * (1.f - wv * e4.z) + wv * a4.z;
    o.w = m.w * (1.f - wv * e4.w) + wv * a4.w;
    ((float4*)mem_out)[i4] = o;
}

// ---------------------------------------------------------------------------
extern "C" void kernel_launch(void* const* d_in, const int* in_sizes, int n_in,
                              void* d_out, int out_size) {
    const float* h      = (const float*)d_in[0];
    const float* w_prev = (const float*)d_in[1];
    const float* memory = (const float*)d_in[2];
    const float* Wm     = (const float*)d_in[3];
    const float* bias   = (const float*)d_in[4];

    float* w_out   = (float*)d_out;            // [B, N]
    float* mem_out = (float*)d_out + (size_t)B * N;  // [B, N, M]

    k_proj<<<B, 256>>>(h, Wm, bias);
    k_score<<<(B * N) / 16, 256>>>(memory);
    k_addr<<<B, 512>>>(w_prev, w_out);
    k_write<<<(B * N * M / 4) / 256, 256>>>(memory, w_out, mem_out);
}

// round 3
// speedup vs baseline: 1.3914x; 1.3914x over previous
#include <cuda_runtime.h>
#include <math.h>
#include <float.h>

#define B 256
#define N 2048
#define M 64
#define C 512
#define OUTD 198   // 3*M + 6

// Param scratch layout per batch (stride 208):
//  [0..63]   k (raw)
//  [64..127] e = sigmoid(o[70..133])
//  [128..191] a = o[134..197]
//  [192] beta  [193] g  [194] gamma  [195..197] s0,s1,s2  [198] ||k+eps||
#define P_STRIDE 208
__device__ float g_params[B * P_STRIDE];
__device__ float g_scores[B * N];

__device__ __forceinline__ float softplus_f(float x) {
    return (x > 20.f) ? x : log1pf(expf(x));
}
__device__ __forceinline__ float sigmoid_f(float x) {
    return 1.f / (1.f + __expf(-x));
}

// ---------------------------------------------------------------------------
// Kernel 1: controller projection o = h @ W^T + b, activations, k-norm.
// Grid (128, 2): x = batch-pair (2 batches share each W read -> 4 FMA/load),
// y = output chunk: y==0 -> j in [0,70) (k + scalars), y==1 -> j in [70,198)
// (e, a). W L2 traffic: 64 pair-tiles * 405KB = 26 MB.
// ---------------------------------------------------------------------------
__global__ void k_proj(const float* __restrict__ h,
                       const float* __restrict__ Wm,
                       const float* __restrict__ bias) {
    int b0 = blockIdx.x * 2;
    int by = blockIdx.y;
    __shared__ float sh[2][C];
    __shared__ float so[2][128];

    for (int i = threadIdx.x; i < 2 * C; i += 256)
        sh[i >> 9][i & (C - 1)] = h[(size_t)b0 * C + i];
    __syncthreads();

    int warp = threadIdx.x >> 5, lane = threadIdx.x & 31;
    int jbase = by ? 70 : 0;
    int jcount = by ? 128 : 70;

    for (int jj = warp; jj < jcount; jj += 8) {
        const float* wr = Wm + (size_t)(jbase + jj) * C;
        float a0 = 0.f, a1 = 0.f;
        #pragma unroll 8
        for (int c = lane; c < C; c += 32) {
            float wv = wr[c];
            a0 += wv * sh[0][c];
            a1 += wv * sh[1][c];
        }
        #pragma unroll
        for (int o = 16; o; o >>= 1) {
            a0 += __shfl_xor_sync(0xffffffffu, a0, o);
            a1 += __shfl_xor_sync(0xffffffffu, a1, o);
        }
        if (lane == 0) {
            float bv = bias[jbase + jj];
            so[0][jj] = a0 + bv;
            so[1][jj] = a1 + bv;
        }
    }
    __syncthreads();

    int t = threadIdx.x;
    if (by == 0) {
        // so[bb][0..63]=k, [64]=beta, [65]=g, [66..68]=s, [69]=gamma
        if (t < 128) {
            int bb = t >> 6;
            g_params[(b0 + bb) * P_STRIDE + (t & 63)] = so[bb][t & 63];
        } else if (t == 128 || t == 129) {
            int bb = t - 128;
            float* p = g_params + (b0 + bb) * P_STRIDE;
            p[192] = softplus_f(so[bb][64]);          // beta
            p[193] = sigmoid_f(so[bb][65]);           // g
            p[194] = 1.f + softplus_f(so[bb][69]);    // gamma
            float s0 = so[bb][66], s1 = so[bb][67], s2 = so[bb][68];
            float mx = fmaxf(s0, fmaxf(s1, s2));
            float e0 = __expf(s0 - mx), e1 = __expf(s1 - mx), e2 = __expf(s2 - mx);
            float inv = 1.f / (e0 + e1 + e2);
            p[195] = e0 * inv; p[196] = e1 * inv; p[197] = e2 * inv;
        }
        if (warp < 2) {   // ||k + 1e-16|| per batch
            int bb = warp;
            float v0 = so[bb][lane] + 1e-16f;
            float v1 = so[bb][lane + 32] + 1e-16f;
            float acc = v0 * v0 + v1 * v1;
            #pragma unroll
            for (int o = 16; o; o >>= 1) acc += __shfl_xor_sync(0xffffffffu, acc, o);
            if (lane == 0) g_params[(b0 + bb) * P_STRIDE + 198] = sqrtf(acc);
        }
    } else {
        // so[bb][0..63]=e-pre (j 70..133), so[bb][64..127]=a (j 134..197)
        int bb = t >> 7, tt = t & 127;
        float* p = g_params + (b0 + bb) * P_STRIDE;
        if (tt < 64) p[64 + tt] = sigmoid_f(so[bb][tt]);
        else         p[128 + (tt - 64)] = so[bb][tt];
    }
}

// ---------------------------------------------------------------------------
// Kernel 2: content-addressing scores. Streams memory (134 MB) once.
// Grid = B*8 blocks; each block covers 256 rows of one batch (64 KB).
// 8 warps; each warp covers 32 rows = 16 row-pairs, looped with 4-deep
// prefetch (MLP>=4). 16 lanes per row, float4 loads.
// ---------------------------------------------------------------------------
__global__ void k_score(const float* __restrict__ memory) {
    int b = blockIdx.x >> 3;
    int seg = blockIdx.x & 7;
    int warp = threadIdx.x >> 5, lane = threadIdx.x & 31;
    int half = lane >> 4, q = lane & 15;

    __shared__ float sk[64];
    __shared__ float sbk[2];    // beta, knorm
    if (threadIdx.x < 64) sk[threadIdx.x] = g_params[b * P_STRIDE + threadIdx.x] + 1e-16f;
    if (threadIdx.x == 64) sbk[0] = g_params[b * P_STRIDE + 192];
    if (threadIdx.x == 65) sbk[1] = g_params[b * P_STRIDE + 198];
    __syncthreads();

    float4 kv = ((const float4*)sk)[q];
    float beta = sbk[0], knorm = sbk[1];

    int row0 = seg * 256 + warp * 32 + half;           // local row for ii=0
    const float4* mp = (const float4*)(memory + ((size_t)b * N + row0) * M) + q;
    float* sp = g_scores + (size_t)b * N + row0;

    #pragma unroll
    for (int ii = 0; ii < 16; ii += 4) {
        float4 mm[4];
        #pragma unroll
        for (int u = 0; u < 4; u++)
            mm[u] = mp[(size_t)(ii + u) * 2 * 16];      // +2 rows per step, 16 float4/row
        #pragma unroll
        for (int u = 0; u < 4; u++) {
            float x0 = mm[u].x + 1e-16f, x1 = mm[u].y + 1e-16f;
            float x2 = mm[u].z + 1e-16f, x3 = mm[u].w + 1e-16f;
            float dot = x0 * kv.x + x1 * kv.y + x2 * kv.z + x3 * kv.w;
            float nrm = x0 * x0 + x1 * x1 + x2 * x2 + x3 * x3;
            #pragma unroll
            for (int o = 8; o; o >>= 1) {
                dot += __shfl_xor_sync(0xffffffffu, dot, o);
                nrm += __shfl_xor_sync(0xffffffffu, nrm, o);
            }
            if (q == 0) {
                float denom = fmaxf(sqrtf(nrm) * knorm, 1e-8f);
                sp[(ii + u) * 2] = beta * dot / denom;
            }
        }
    }
}

// ---------------------------------------------------------------------------
// Kernel 3: per-batch addressing: softmax(scores), gate with w_prev,
// circular 3-tap shift, sharpen (pow gamma via MUFU), renormalize -> w.
// ---------------------------------------------------------------------------
__device__ __forceinline__ float blockReduce(float v, float* red, bool is_max) {
    int lane = threadIdx.x & 31, wid = threadIdx.x >> 5;
    #pragma unroll
    for (int o = 16; o; o >>= 1) {
        float t = __shfl_xor_sync(0xffffffffu, v, o);
        v = is_max ? fmaxf(v, t) : (v + t);
    }
    if (lane == 0) red[wid] = v;
    __syncthreads();
    float r = (threadIdx.x < 16) ? red[threadIdx.x] : (is_max ? -FLT_MAX : 0.f);
    if (wid == 0) {
        #pragma unroll
        for (int o = 8; o; o >>= 1) {
            float t = __shfl_xor_sync(0xffffffffu, r, o);
            r = is_max ? fmaxf(r, t) : (r + t);
        }
        if (lane == 0) red[0] = r;
    }
    __syncthreads();
    float out = red[0];
    __syncthreads();
    return out;
}

__global__ void k_addr(const float* __restrict__ w_prev, float* __restrict__ w_out) {
    int b = blockIdx.x;
    __shared__ float sw[N];
    __shared__ float red[32];

    const float* sc = g_scores + (size_t)b * N;
    const float* p = g_params + b * P_STRIDE;
    int t = threadIdx.x;

    float v[4];
    float mx = -FLT_MAX;
    #pragma unroll
    for (int i = 0; i < 4; i++) { v[i] = sc[t + i * 512]; mx = fmaxf(mx, v[i]); }
    mx = blockReduce(mx, red, true);

    float sum = 0.f;
    #pragma unroll
    for (int i = 0; i < 4; i++) { v[i] = __expf(v[i] - mx); sum += v[i]; }
    sum = blockReduce(sum, red, false);
    float inv = 1.f / sum;

    float g = p[193];
    #pragma unroll
    for (int i = 0; i < 4; i++) {
        int idx = t + i * 512;
        sw[idx] = g * (v[i] * inv) + (1.f - g) * w_prev[(size_t)b * N + idx];
    }
    __syncthreads();

    float s0 = p[195], s1 = p[196], s2 = p[197], gamma = p[194];
    float u[4];
    float psum = 0.f;
    #pragma unroll
    for (int i = 0; i < 4; i++) {
        int idx = t + i * 512;
        float wt = sw[(idx + N - 1) & (N - 1)] * s0 + sw[idx] * s1 + sw[(idx + 1) & (N - 1)] * s2;
        // wt >= 0 (convex combo of nonneg); wt==0 -> __powf gives 0, correct.
        float ws = __powf(wt, gamma);
        u[i] = ws; psum += ws;
    }
    psum = blockReduce(psum, red, false);
    float invp = 1.f / (psum + 1e-16f);
    #pragma unroll
    for (int i = 0; i < 4; i++)
        w_out[(size_t)b * N + t + i * 512] = u[i] * invp;
}

// ---------------------------------------------------------------------------
// Kernel 4: erase/add write: mem_new = memory*(1 - w (x) e) + w (x) a.
// float4 per thread; w broadcast per row; e/a hit L1. (Already at HBM cap.)
// ---------------------------------------------------------------------------
__global__ void k_write(const float* __restrict__ memory,
                        const float* __restrict__ w,
                        float* __restrict__ mem_out) {
    size_t i4 = (size_t)blockIdx.x * 256 + threadIdx.x;   // float4 index
    int m4 = (int)(i4 & 15);
    size_t row = i4 >> 4;
    int b = (int)(row >> 11);

    float wv = __ldg(w + row);
    const float* p = g_params + b * P_STRIDE;
    float4 e4 = ((const float4*)(p + 64))[m4];
    float4 a4 = ((const float4*)(p + 128))[m4];
    float4 m = ((const float4*)memory)[i4];
    float4 o;
    o.x = m.x * (1.f - wv * e4.x) + wv * a4.x;
    o.y = m.y * (1.f - wv * e4.y) + wv * a4.y;
    o.z = m.z * (1.f - wv * e4.z) + wv * a4.z;
    o.w = m.w * (1.f - wv * e4.w) + wv * a4.w;
    ((float4*)mem_out)[i4] = o;
}

// ---------------------------------------------------------------------------
extern "C" void kernel_launch(void* const* d_in, const int* in_sizes, int n_in,
                              void* d_out, int out_size) {
    const float* h      = (const float*)d_in[0];
    const float* w_prev = (const float*)d_in[1];
    const float* memory = (const float*)d_in[2];
    const float* Wm     = (const float*)d_in[3];
    const float* bias   = (const float*)d_in[4];

    float* w_out   = (float*)d_out;                     // [B, N]
    float* mem_out = (float*)d_out + (size_t)B * N;     // [B, N, M]

    k_proj<<<dim3(B / 2, 2), 256>>>(h, Wm, bias);
    k_score<<<B * 8, 256>>>(memory);
    k_addr<<<B, 512>>>(w_prev, w_out);
    k_write<<<(B * N * M / 4) / 256, 256>>>(memory, w_out, mem_out);
}